// round 4
// baseline (speedup 1.0000x reference)
#include <cuda_runtime.h>

#define NROWS 2048
#define DIN 256
#define H 64
#define HP 32      // h pairs
#define HPAD 66    // float2 row stride in outer smem (528B, 16B-aligned, conflict-free)

// Hidden activations, n-major float4: element [n*16 + hq] holds h = 4hq..4hq+3.
__device__ float4 g_agh[NROWS * 16];
__device__ float4 g_abh[NROWS * 16];

typedef unsigned long long u64;

__device__ __forceinline__ u64 f2add(u64 a, u64 b) {
    u64 d; asm("add.rn.f32x2 %0, %1, %2;" : "=l"(d) : "l"(a), "l"(b)); return d;
}
__device__ __forceinline__ u64 f2fma(u64 a, u64 b, u64 c) {
    u64 d; asm("fma.rn.f32x2 %0, %1, %2, %3;" : "=l"(d) : "l"(a), "l"(b), "l"(c)); return d;
}
__device__ __forceinline__ u64 f2relu(u64 s) {
    float lo, hi;
    asm("mov.b64 {%0, %1}, %2;" : "=f"(lo), "=f"(hi) : "l"(s));
    lo = fmaxf(lo, 0.0f);
    hi = fmaxf(hi, 0.0f);
    u64 d; asm("mov.b64 %0, {%1, %2};" : "=l"(d) : "f"(lo), "f"(hi)); return d;
}

// ---------------------------------------------------------------------------
// Kernel 1 (fused): hidden for BOTH embeddings. 256 blocks:
// [0,128) -> ag (+b1), [128,256) -> ab. 16 rows/block.
// Thread (hq = tid&15, rs = tid>>4): 1 row, 4 h (float4 acc).
// Per kk: 1 LDS.128 (w, conflict-free) + 1 LDS.32 (e, broadcast) + 4 FFMA.
// K tiled by 128 with register prefetch of tile 1.
// ---------------------------------------------------------------------------
__global__ void __launch_bounds__(256) hidden_kernel(
    const float* __restrict__ ag, const float* __restrict__ ab,
    const float* __restrict__ W1, const float* __restrict__ b1)
{
    __shared__ float  embs[16][128];    //  8 KB
    __shared__ float4 w1s[128][16];     // 32 KB

    const int tid = threadIdx.x;
    const int hq  = tid & 15;
    const int rs  = tid >> 4;
    const int which = blockIdx.x >> 7;
    const int n0  = (blockIdx.x & 127) * 16;
    const int koff = which ? DIN : 0;
    const float* __restrict__ emb = which ? ab : ag;

    float4 acc;
    if (which == 0) acc = ((const float4*)b1)[hq];
    else            acc = make_float4(0.f, 0.f, 0.f, 0.f);

    float4 e_pf[2], w_pf[8];

    // ---- tile 0 -> regs -> smem ----
    #pragma unroll
    for (int t = 0; t < 2; t++) {
        int idx = tid + t * 256, r = idx >> 5, c4 = idx & 31;
        e_pf[t] = ((const float4*)(emb + (size_t)(n0 + r) * DIN))[c4];
    }
    #pragma unroll
    for (int t = 0; t < 8; t++) {
        int idx = tid + t * 256, kk = idx >> 4, q = idx & 15;
        w_pf[t] = ((const float4*)(W1 + (size_t)(koff + kk) * H))[q];
    }
    #pragma unroll
    for (int t = 0; t < 2; t++) {
        int idx = tid + t * 256, r = idx >> 5, c4 = idx & 31;
        ((float4*)&embs[r][c4 * 4])[0] = e_pf[t];
    }
    #pragma unroll
    for (int t = 0; t < 8; t++) {
        int idx = tid + t * 256, kk = idx >> 4, q = idx & 15;
        w1s[kk][q] = w_pf[t];
    }
    __syncthreads();

    // ---- prefetch tile 1 ----
    #pragma unroll
    for (int t = 0; t < 2; t++) {
        int idx = tid + t * 256, r = idx >> 5, c4 = idx & 31;
        e_pf[t] = ((const float4*)(emb + (size_t)(n0 + r) * DIN + 128))[c4];
    }
    #pragma unroll
    for (int t = 0; t < 8; t++) {
        int idx = tid + t * 256, kk = idx >> 4, q = idx & 15;
        w_pf[t] = ((const float4*)(W1 + (size_t)(koff + 128 + kk) * H))[q];
    }

    // ---- compute tile 0 ----
    #pragma unroll 32
    for (int kk = 0; kk < 128; kk++) {
        float4 w = w1s[kk][hq];
        float e = embs[rs][kk];
        acc.x = fmaf(e, w.x, acc.x);
        acc.y = fmaf(e, w.y, acc.y);
        acc.z = fmaf(e, w.z, acc.z);
        acc.w = fmaf(e, w.w, acc.w);
    }
    __syncthreads();

    // ---- tile 1 -> smem, compute ----
    #pragma unroll
    for (int t = 0; t < 2; t++) {
        int idx = tid + t * 256, r = idx >> 5, c4 = idx & 31;
        ((float4*)&embs[r][c4 * 4])[0] = e_pf[t];
    }
    #pragma unroll
    for (int t = 0; t < 8; t++) {
        int idx = tid + t * 256, kk = idx >> 4, q = idx & 15;
        w1s[kk][q] = w_pf[t];
    }
    __syncthreads();

    #pragma unroll 32
    for (int kk = 0; kk < 128; kk++) {
        float4 w = w1s[kk][hq];
        float e = embs[rs][kk];
        acc.x = fmaf(e, w.x, acc.x);
        acc.y = fmaf(e, w.y, acc.y);
        acc.z = fmaf(e, w.z, acc.z);
        acc.w = fmaf(e, w.w, acc.w);
    }

    float4* outh = which ? g_abh : g_agh;
    outh[(size_t)(n0 + rs) * 16 + hq] = acc;
}

// ---------------------------------------------------------------------------
// Kernel 2: out[n,m] = sigmoid( sum_h relu(ag_h[n,h]+ab_h[m,h]) * W2[h] + b2 )
// 64x64 tile, 256 threads, 4x4 outputs/thread, h in f32x2 pairs.
// Smem [hp][n] with row stride HPAD=66 float2 (16B-aligned): a-loads are
// 2x LDS.128 (broadcast), b-loads 4x LDS.64 (conflict-free), w 1x LDS.64.
// ---------------------------------------------------------------------------
__global__ void __launch_bounds__(256, 4) outer_kernel(
    const float* __restrict__ W2, const float* __restrict__ b2,
    float* __restrict__ out)
{
    __shared__ float2 ags[HP * HPAD];
    __shared__ float2 abss[HP * HPAD];
    __shared__ float2 w2s[HP];

    const int tid = threadIdx.x;
    const int n0 = blockIdx.y * 64;
    const int m0 = blockIdx.x * 64;

    // fill (transpose): read [n][hq] float4 (coalesced), write [hp][n]
    const ulonglong2* gA = (const ulonglong2*)g_agh;
    const ulonglong2* gB = (const ulonglong2*)g_abh;
    u64* agsu  = (u64*)ags;
    u64* abssu = (u64*)abss;
    #pragma unroll
    for (int t = 0; t < 4; t++) {
        int idx = tid + t * 256;            // 0..1023
        int r = idx >> 4, hq = idx & 15;    // row 0..63, hq 0..15 (2 hp each)
        ulonglong2 va = gA[(size_t)(n0 + r) * 16 + hq];
        ulonglong2 vb = gB[(size_t)(m0 + r) * 16 + hq];
        agsu[(2 * hq) * HPAD + r]      = va.x;
        agsu[(2 * hq + 1) * HPAD + r]  = va.y;
        abssu[(2 * hq) * HPAD + r]     = vb.x;
        abssu[(2 * hq + 1) * HPAD + r] = vb.y;
    }
    if (tid < HP) w2s[tid] = ((const float2*)W2)[tid];
    __syncthreads();

    const int tx = tid & 15;   // m: m_local = tx + 16*j
    const int ty = tid >> 4;   // n: n_local = ty*4 + i

    const u64* aB = agsu + ty * 4;
    const u64* bB = abssu + tx;
    const u64* w2u = (const u64*)w2s;

    u64 acc[4][4];
    #pragma unroll
    for (int i = 0; i < 4; i++)
        #pragma unroll
        for (int j = 0; j < 4; j++) acc[i][j] = 0ull;

    #pragma unroll 8
    for (int hp = 0; hp < HP; hp++) {
        u64 w = w2u[hp];
        ulonglong2 a01 = *(const ulonglong2*)(aB + hp * HPAD);
        ulonglong2 a23 = *(const ulonglong2*)(aB + hp * HPAD + 2);
        u64 a[4] = { a01.x, a01.y, a23.x, a23.y };
        u64 b[4];
        #pragma unroll
        for (int j = 0; j < 4; j++) b[j] = bB[hp * HPAD + 16 * j];
        #pragma unroll
        for (int i = 0; i < 4; i++)
            #pragma unroll
            for (int j = 0; j < 4; j++)
                acc[i][j] = f2fma(f2relu(f2add(a[i], b[j])), w, acc[i][j]);
    }

    const float b2v = *b2;
    #pragma unroll
    for (int i = 0; i < 4; i++) {
        int n = n0 + ty * 4 + i;
        #pragma unroll
        for (int j = 0; j < 4; j++) {
            float lo, hi;
            asm("mov.b64 {%0, %1}, %2;" : "=f"(lo), "=f"(hi) : "l"(acc[i][j]));
            float logit = lo + hi + b2v;
            out[(size_t)n * 2048 + m0 + tx + 16 * j] = 1.0f / (1.0f + __expf(-logit));
        }
    }
}

extern "C" void kernel_launch(void* const* d_in, const int* in_sizes, int n_in,
                              void* d_out, int out_size)
{
    const float* ag = (const float*)d_in[0];
    const float* ab = (const float*)d_in[1];
    const float* W1 = (const float*)d_in[2];
    const float* b1 = (const float*)d_in[3];
    const float* W2 = (const float*)d_in[4];
    const float* b2 = (const float*)d_in[5];
    float* out = (float*)d_out;

    hidden_kernel<<<256, 256>>>(ag, ab, W1, b1);

    dim3 grid(2048 / 64, 2048 / 64);
    outer_kernel<<<grid, 256>>>(W2, b2, out);
}

// round 6
// speedup vs baseline: 1.2143x; 1.2143x over previous
#include <cuda_runtime.h>

#define NROWS 2048
#define DIN 256
#define H 64
#define HP 32   // h pairs
#define HQ 16   // h quads (2 pairs)

// Hidden activations, interleaved for the outer kernel:
// ulonglong2 entry [hq*2048 + n] = { float2(h=4hq,4hq+1), float2(h=4hq+2,4hq+3) }
__device__ ulonglong2 g_agh[HQ * NROWS];
__device__ ulonglong2 g_abh[HQ * NROWS];

typedef unsigned long long u64;

__device__ __forceinline__ u64 f2add(u64 a, u64 b) {
    u64 d; asm("add.rn.f32x2 %0, %1, %2;" : "=l"(d) : "l"(a), "l"(b)); return d;
}
__device__ __forceinline__ u64 f2fma(u64 a, u64 b, u64 c) {
    u64 d; asm("fma.rn.f32x2 %0, %1, %2, %3;" : "=l"(d) : "l"(a), "l"(b), "l"(c)); return d;
}
__device__ __forceinline__ u64 f2relu(u64 s) {
    float lo, hi;
    asm("mov.b64 {%0, %1}, %2;" : "=f"(lo), "=f"(hi) : "l"(s));
    lo = fmaxf(lo, 0.0f);
    hi = fmaxf(hi, 0.0f);
    u64 d; asm("mov.b64 %0, {%1, %2};" : "=l"(d) : "f"(lo), "f"(hi)); return d;
}

// ---------------------------------------------------------------------------
// Kernel 1 (fused): hidden for BOTH embeddings (R2-proven body).
// blocks [0,128) -> ag (+b1), [128,256) -> ab. 16 rows/block.
// Thread: hp = tid&31, rows ng, ng+8. K tiled by 128.
// Stores go to the interleaved [hq][n] layout (float2 halves of ulonglong2).
// ---------------------------------------------------------------------------
__global__ void __launch_bounds__(256) hidden_kernel(
    const float* __restrict__ ag, const float* __restrict__ ab,
    const float* __restrict__ W1, const float* __restrict__ b1)
{
    __shared__ float  embs[16][128];    //  8 KB
    __shared__ float2 w1s[128][32];     // 32 KB

    const int tid = threadIdx.x;
    const int hp  = tid & 31;
    const int ng  = tid >> 5;           // 0..7
    const int which = blockIdx.x >> 7;  // 0 = ag, 1 = ab
    const int n0  = (blockIdx.x & 127) * 16;
    const int koff = which ? DIN : 0;
    const float* __restrict__ emb = which ? ab : ag;

    float acc00, acc01, acc10, acc11;
    if (which == 0) {
        float2 bv = ((const float2*)b1)[hp];
        acc00 = bv.x; acc01 = bv.y; acc10 = bv.x; acc11 = bv.y;
    } else {
        acc00 = acc01 = acc10 = acc11 = 0.0f;
    }

    for (int kb = 0; kb < 2; kb++) {
        #pragma unroll
        for (int t = 0; t < 2; t++) {
            int idx = tid + t * 256, r = idx >> 5, c4 = idx & 31;
            ((float4*)&embs[r][c4 * 4])[0] =
                ((const float4*)(emb + (size_t)(n0 + r) * DIN + kb * 128))[c4];
        }
        #pragma unroll
        for (int t = 0; t < 8; t++) {
            int idx = tid + t * 256, kk = idx >> 4, q = idx & 15;
            ((float4*)&w1s[kk][0])[q] =
                ((const float4*)(W1 + (size_t)(koff + kb * 128 + kk) * H))[q];
        }
        __syncthreads();

        #pragma unroll 16
        for (int kk = 0; kk < 128; kk++) {
            float2 w = w1s[kk][hp];
            float e0 = embs[ng][kk];
            float e1 = embs[ng + 8][kk];
            acc00 += e0 * w.x;  acc01 += e0 * w.y;
            acc10 += e1 * w.x;  acc11 += e1 * w.y;
        }
        __syncthreads();
    }

    // interleaved store: float2 half (hp&1) of entry [hp>>1][n]
    float2* outh = (float2*)(which ? g_abh : g_agh);
    size_t base = (size_t)(hp >> 1) * NROWS;
    outh[(base + n0 + ng)     * 2 + (hp & 1)] = make_float2(acc00, acc01);
    outh[(base + n0 + ng + 8) * 2 + (hp & 1)] = make_float2(acc10, acc11);
}

// ---------------------------------------------------------------------------
// Kernel 2: out[n,m] = sigmoid( sum_h relu(ag_h[n,h]+ab_h[m,h]) * W2[h] + b2 )
// 64x64 tile, 256 threads, 4x4 outputs/thread.
// Smem [hq][n] ulonglong2 (4 h per entry): fill is a direct coalesced 16B
// copy; main loop uses 9 LDS.128 per hq (4 a broadcast, 4 b conflict-free,
// 1 w broadcast) + 128 math slots. Unroll 2 keeps body < 6KB L0.
// ---------------------------------------------------------------------------
__global__ void __launch_bounds__(256) outer_kernel(
    const float* __restrict__ W2, const float* __restrict__ b2,
    float* __restrict__ out)
{
    __shared__ ulonglong2 a_s[HQ][64];   // 16 KB
    __shared__ ulonglong2 b_s[HQ][64];   // 16 KB
    __shared__ float2 w2s[HP];

    const int tid = threadIdx.x;
    const int n0 = blockIdx.y * 64;
    const int m0 = blockIdx.x * 64;

    // direct fill: entry [hq][r] <- gmem [hq*2048 + n0/m0 + r] (coalesced)
    #pragma unroll
    for (int t = 0; t < 4; t++) {
        int idx = tid + t * 256;            // 0..1023
        int hq = idx >> 6, r = idx & 63;
        a_s[hq][r] = g_agh[(size_t)hq * NROWS + n0 + r];
        b_s[hq][r] = g_abh[(size_t)hq * NROWS + m0 + r];
    }
    if (tid < HP) w2s[tid] = ((const float2*)W2)[tid];
    __syncthreads();

    const int tx = tid & 15;   // m: m_local = tx + 16*j
    const int ty = tid >> 4;   // n: n_local = ty*4 + i
    const ulonglong2* w2q = (const ulonglong2*)w2s;

    u64 acc[4][4];
    #pragma unroll
    for (int i = 0; i < 4; i++)
        #pragma unroll
        for (int j = 0; j < 4; j++) acc[i][j] = 0ull;

    #pragma unroll 2
    for (int hq = 0; hq < HQ; hq++) {
        ulonglong2 wv = w2q[hq];
        ulonglong2 b[4];
        #pragma unroll
        for (int j = 0; j < 4; j++) b[j] = b_s[hq][tx + 16 * j];
        #pragma unroll
        for (int i = 0; i < 4; i++) {
            ulonglong2 av = a_s[hq][ty * 4 + i];
            #pragma unroll
            for (int j = 0; j < 4; j++) {
                acc[i][j] = f2fma(f2relu(f2add(av.x, b[j].x)), wv.x, acc[i][j]);
                acc[i][j] = f2fma(f2relu(f2add(av.y, b[j].y)), wv.y, acc[i][j]);
            }
        }
    }

    const float b2v = *b2;
    #pragma unroll
    for (int i = 0; i < 4; i++) {
        int n = n0 + ty * 4 + i;
        #pragma unroll
        for (int j = 0; j < 4; j++) {
            float lo, hi;
            asm("mov.b64 {%0, %1}, %2;" : "=f"(lo), "=f"(hi) : "l"(acc[i][j]));
            float logit = lo + hi + b2v;
            out[(size_t)n * 2048 + m0 + tx + 16 * j] = 1.0f / (1.0f + __expf(-logit));
        }
    }
}

extern "C" void kernel_launch(void* const* d_in, const int* in_sizes, int n_in,
                              void* d_out, int out_size)
{
    const float* ag = (const float*)d_in[0];
    const float* ab = (const float*)d_in[1];
    const float* W1 = (const float*)d_in[2];
    const float* b1 = (const float*)d_in[3];
    const float* W2 = (const float*)d_in[4];
    const float* b2 = (const float*)d_in[5];
    float* out = (float*)d_out;

    hidden_kernel<<<256, 256>>>(ag, ab, W1, b1);

    dim3 grid(2048 / 64, 2048 / 64);
    outer_kernel<<<grid, 256>>>(W2, b2, out);
}